// round 13
// baseline (speedup 1.0000x reference)
#include <cuda_runtime.h>
#include <cuda_fp16.h>
#include <math.h>
#include <stdint.h>

// Problem dims (fixed by the dataset)
#define BB   16
#define TT   1024
#define DD   256        // key_dim == e_dim
#define NE   512        // codebook size
#define MR   (BB*TT)    // 16384 rows

// ---------------- scratch (__device__ globals: allocation-free) ----------------
__device__ __half g_ksn_h[MR * DD];     // normalized key_soft, fp16
__device__ float  g_ksn_f[MR * DD];     // normalized key_soft, fp32 (argmax check)
__device__ __half g_wh[MR * NE];        // softmax weights fp16
__device__ __half g_keys_h[NE * DD];
__device__ float  g_keys_f[NE * DD];    // fp32 keys_norm (argmax check)
__device__ float  g_vp_norm[NE * DD];   // fp32 (exact gather source)
__device__ __half g_vpn_h[NE * DD];
__device__ __half g_vpnT_h[DD * NE];    // vp_norm transposed fp16 [E, n_e]
__device__ __half g_vwh[MR * DD];       // normalized vparams_w fp16

// =============================== aux kernels ===================================
// L2 normalize, 256 cols, 2 rows per warp (MLP=2); optional fp32 + fp16 outputs
__global__ void rownorm_hl(const float* __restrict__ in, float* __restrict__ of,
                           __half* __restrict__ oh, int nrows) {
    long w = (long)((blockIdx.x * blockDim.x + threadIdx.x) >> 5) * 2;
    int lane = threadIdx.x & 31;
    if (w >= nrows) return;
    const float4* ip0 = (const float4*)(in + w * 256);
    const float4* ip1 = (const float4*)(in + (w + 1) * 256);
    float4 a0 = ip0[lane], a1 = ip0[lane + 32];
    float4 b0 = ip1[lane], b1 = ip1[lane + 32];
    float s0 = a0.x*a0.x + a0.y*a0.y + a0.z*a0.z + a0.w*a0.w
             + a1.x*a1.x + a1.y*a1.y + a1.z*a1.z + a1.w*a1.w;
    float s1 = b0.x*b0.x + b0.y*b0.y + b0.z*b0.z + b0.w*b0.w
             + b1.x*b1.x + b1.y*b1.y + b1.z*b1.z + b1.w*b1.w;
    #pragma unroll
    for (int o = 16; o; o >>= 1) {
        s0 += __shfl_xor_sync(0xffffffffu, s0, o);
        s1 += __shfl_xor_sync(0xffffffffu, s1, o);
    }
    float k0 = 1.0f / fmaxf(sqrtf(s0), 1e-12f);
    float k1 = 1.0f / fmaxf(sqrtf(s1), 1e-12f);
    float4 r0 = make_float4(a0.x*k0, a0.y*k0, a0.z*k0, a0.w*k0);
    float4 r1 = make_float4(a1.x*k0, a1.y*k0, a1.z*k0, a1.w*k0);
    float4 r2 = make_float4(b0.x*k1, b0.y*k1, b0.z*k1, b0.w*k1);
    float4 r3 = make_float4(b1.x*k1, b1.y*k1, b1.z*k1, b1.w*k1);
    if (of) {
        float4* op0 = (float4*)(of + w * 256);
        float4* op1 = (float4*)(of + (w + 1) * 256);
        op0[lane] = r0; op0[lane + 32] = r1;
        op1[lane] = r2; op1[lane + 32] = r3;
    }
    __half2* hp0 = (__half2*)(oh + w * 256);
    __half2* hp1 = (__half2*)(oh + (w + 1) * 256);
    hp0[lane*2]        = __floats2half2_rn(r0.x, r0.y);
    hp0[lane*2+1]      = __floats2half2_rn(r0.z, r0.w);
    hp0[64 + lane*2]   = __floats2half2_rn(r1.x, r1.y);
    hp0[64 + lane*2+1] = __floats2half2_rn(r1.z, r1.w);
    hp1[lane*2]        = __floats2half2_rn(r2.x, r2.y);
    hp1[lane*2+1]      = __floats2half2_rn(r2.z, r2.w);
    hp1[64 + lane*2]   = __floats2half2_rn(r3.x, r3.y);
    hp1[64 + lane*2+1] = __floats2half2_rn(r3.z, r3.w);
}

__global__ void transpose_vp() {
    __shared__ float tile[32][33];
    int x = blockIdx.x * 32 + threadIdx.x;
    int y = blockIdx.y * 32 + threadIdx.y;
    tile[threadIdx.y][threadIdx.x] = g_vp_norm[y * 256 + x];
    __syncthreads();
    int tx = blockIdx.y * 32 + threadIdx.x;
    int ty = blockIdx.x * 32 + threadIdx.y;
    g_vpnT_h[ty * 512 + tx] = __float2half_rn(tile[threadIdx.x][threadIdx.y]);
}

// warp-per-row softmax + exact-argmax (fp32 candidate re-check) + hard gather
__global__ void softmax_argmax(const float* __restrict__ ksh,
                               float* __restrict__ out_idx,
                               float* __restrict__ out_hard) {
    int r = (blockIdx.x * blockDim.x + threadIdx.x) >> 5;
    int lane = threadIdx.x & 31;
    if (r >= MR) return;
    const float4* row4 = (const float4*)(ksh + (long)r * NE);
    float4 v[4];
    #pragma unroll
    for (int i = 0; i < 4; i++) v[i] = row4[i * 32 + lane];
    // warp max
    float m = -2e30f;
    #pragma unroll
    for (int i = 0; i < 4; i++)
        m = fmaxf(m, fmaxf(fmaxf(v[i].x, v[i].y), fmaxf(v[i].z, v[i].w)));
    #pragma unroll
    for (int o = 16; o; o >>= 1) m = fmaxf(m, __shfl_xor_sync(0xffffffffu, m, o));

    // fp32 query row (for exact re-check)
    const float4* xr4 = (const float4*)(g_ksn_f + (long)r * 256);
    float4 x0 = xr4[lane * 2], x1 = xr4[lane * 2 + 1];

    // candidate mask: fp16 dot error (input rounding + fp16-acc chain) << eps
    const float eps = 8e-3f;
    unsigned pend = 0;
    #pragma unroll
    for (int i = 0; i < 4; i++) {
        if (v[i].x >= m - eps) pend |= 1u << (i * 4 + 0);
        if (v[i].y >= m - eps) pend |= 1u << (i * 4 + 1);
        if (v[i].z >= m - eps) pend |= 1u << (i * 4 + 2);
        if (v[i].w >= m - eps) pend |= 1u << (i * 4 + 3);
    }
    float bv = -2e30f; int bi = 1 << 30;
    while (true) {
        unsigned act = __ballot_sync(0xffffffffu, pend != 0);
        if (!act) break;
        int leader = __ffs(act) - 1;
        int slot = (pend ? __ffs(pend) - 1 : 0);
        slot = __shfl_sync(0xffffffffu, slot, leader);
        int j = (slot >> 2) * 128 + leader * 4 + (slot & 3);
        const float4* kp = (const float4*)(g_keys_f + (long)j * 256);
        float4 u0 = kp[lane * 2], u1 = kp[lane * 2 + 1];
        float d = u0.x*x0.x + u0.y*x0.y + u0.z*x0.z + u0.w*x0.w
                + u1.x*x1.x + u1.y*x1.y + u1.z*x1.z + u1.w*x1.w;
        #pragma unroll
        for (int o = 16; o; o >>= 1) d += __shfl_xor_sync(0xffffffffu, d, o);
        if (d > bv || (d == bv && j < bi)) { bv = d; bi = j; }
        if (lane == leader) pend &= pend - 1;
    }

    // softmax (fp16-accurate scores: fine for w)
    float e[16];
    float sum = 0.0f;
    #pragma unroll
    for (int i = 0; i < 4; i++) {
        e[i*4+0] = expf(v[i].x - m); e[i*4+1] = expf(v[i].y - m);
        e[i*4+2] = expf(v[i].z - m); e[i*4+3] = expf(v[i].w - m);
        sum += e[i*4+0] + e[i*4+1] + e[i*4+2] + e[i*4+3];
    }
    #pragma unroll
    for (int o = 16; o; o >>= 1) sum += __shfl_xor_sync(0xffffffffu, sum, o);
    float inv = 1.0f / sum;
    __half2* wp = (__half2*)(g_wh + (long)r * NE);
    #pragma unroll
    for (int i = 0; i < 4; i++) {
        wp[i*64 + lane*2]     = __floats2half2_rn(e[i*4+0]*inv, e[i*4+1]*inv);
        wp[i*64 + lane*2 + 1] = __floats2half2_rn(e[i*4+2]*inv, e[i*4+3]*inv);
    }
    if (lane == 0) out_idx[r] = (float)bi;
    const float4* vp4 = (const float4*)(g_vp_norm + (long)bi * 256);
    float4* oh4 = (float4*)(out_hard + (long)r * 256);
    oh4[lane*2]     = vp4[lane*2];
    oh4[lane*2 + 1] = vp4[lane*2 + 1];
}

// ============= fp16 mma.sync GEMM with ldmatrix (m16n8k16, sm_80+) =============
// PERSISTENT tile loop: tile < nsCount -> nonsym; else symmetric Gram (batched).
// Block tile 128x128, BK=32, 3-stage cp.async, 8 warps x (64x32), 2 CTAs/SM.
// ACC16: fp16 accumulators chained across the whole k-loop; promoted once.
__device__ __forceinline__ void cp16(uint32_t saddr, const void* g) {
    asm volatile("cp.async.cg.shared.global [%0], [%1], 16;"
                 :: "r"(saddr), "l"(g) : "memory");
}
__device__ __forceinline__ void ldsm4(uint32_t* r, uint32_t addr) {
    asm volatile("ldmatrix.sync.aligned.m8n8.x4.shared.b16 {%0,%1,%2,%3}, [%4];"
                 : "=r"(r[0]), "=r"(r[1]), "=r"(r[2]), "=r"(r[3]) : "r"(addr));
}
__device__ __forceinline__ void mma16(float* d, const uint32_t* a, const uint32_t* b) {
    asm volatile(
        "mma.sync.aligned.m16n8k16.row.col.f32.f16.f16.f32 "
        "{%0,%1,%2,%3}, {%4,%5,%6,%7}, {%8,%9}, {%0,%1,%2,%3};"
        : "+f"(d[0]), "+f"(d[1]), "+f"(d[2]), "+f"(d[3])
        : "r"(a[0]), "r"(a[1]), "r"(a[2]), "r"(a[3]), "r"(b[0]), "r"(b[1]));
}
__device__ __forceinline__ void mma16h(uint32_t* d, const uint32_t* a, const uint32_t* b) {
    asm volatile(
        "mma.sync.aligned.m16n8k16.row.col.f16.f16.f16.f16 "
        "{%0,%1}, {%2,%3,%4,%5}, {%6,%7}, {%0,%1};"
        : "+r"(d[0]), "+r"(d[1])
        : "r"(a[0]), "r"(a[1]), "r"(a[2]), "r"(a[3]), "r"(b[0]), "r"(b[1]));
}

#define STAGE_B 16384   // bytes per stage (A 8192 + B 8192)
#define NSLOTS  296     // 148 SMs x 2 CTAs

template<bool ACC16>
__global__ __launch_bounds__(256, 2) void gemm_h(
    const __half* __restrict__ A_ns, const __half* __restrict__ B_ns,
    float* __restrict__ C_ns, int K, int ldC, int ntX, int nsCount, int nTiles,
    const __half* __restrict__ A_s, float* __restrict__ C_s)
{
    extern __shared__ uint32_t smu[];
    const int t = threadIdx.x;
    const int wid = t >> 5, lane = t & 31;
    const int g = lane >> 2, q = lane & 3;

    uint32_t smb = (uint32_t)__cvta_generic_to_shared(smu);

    // ---- tile-invariant writer precompute (4 x 16B cp.async per thread)
    const int wr = t >> 2, wc = t & 3;                   // row 0..63, chunk 0..3
    const uint32_t wdst = (uint32_t)(wr * 64 + ((wc ^ ((wr >> 1) & 3)) << 4));
    const long  gsrc = (long)wr * K + wc * 8;            // halves
    const long  gstep = (long)64 * K;

    // ---- tile-invariant reader precompute (ldmatrix lane addresses)
    const int mbase = (wid >> 2) * 64, nbase = (wid & 3) * 32;
    const int rA  = (lane & 7) + ((lane >> 3) & 1) * 8;  // row within 16-row tile
    const int cA  = lane >> 4;                           // k-chunk bit
    const int swA = (rA >> 1) & 3;
    const uint32_t laneA = (uint32_t)((mbase + rA) * 64);
    const int rB  = ((lane >> 4) << 3) + (lane & 7);
    const int cB  = (lane >> 3) & 1;
    const int swB = (rB >> 1) & 3;
    const uint32_t laneB = (uint32_t)(8192 + (nbase + rB) * 64);
    const uint32_t koffA0 = (uint32_t)(((0 + cA) ^ swA) << 4);
    const uint32_t koffA1 = (uint32_t)(((2 + cA) ^ swA) << 4);
    const int nk = K >> 5;                // >= 8 here

    for (int tile = blockIdx.x; tile < nTiles; tile += gridDim.x) {
        const bool sym = (tile >= nsCount);
        int bi, bj;
        const __half *Ah, *Bh;
        long csOff = 0;
        if (!sym) {
            bi = tile / ntX; bj = tile % ntX;
            Ah = A_ns + (long)(bi * 128) * K;
            Bh = B_ns + (long)(bj * 128) * K;
        } else {
            int xs = tile - nsCount;
            int bz = xs / 36, u = xs % 36, i = 0;
            while (u >= 8 - i) { u -= 8 - i; i++; }  // 36 pairs, i<=j
            bi = i; bj = i + u;
            const __half* base = A_s + (long)bz * TT * DD;   // K == DD here
            Ah = base + (long)(bi * 128) * K;
            Bh = base + (long)(bj * 128) * K;
            csOff = (long)bz * TT * TT;
        }

        auto issue = [&](int kc, int st) {
            uint32_t sb = smb + (uint32_t)st * STAGE_B;
            const __half* ap = Ah + gsrc + kc * 32;
            const __half* bp = Bh + gsrc + kc * 32;
            cp16(sb + wdst,        ap);
            cp16(sb + wdst + 4096, ap + gstep);
            cp16(sb + 8192 + wdst,        bp);
            cp16(sb + 8192 + wdst + 4096, bp + gstep);
            asm volatile("cp.async.commit_group;" ::: "memory");
        };

        float    accf[4][4][4];
        uint32_t acch[4][4][2];
        if constexpr (ACC16) {
            #pragma unroll
            for (int mi = 0; mi < 4; mi++)
                #pragma unroll
                for (int ni = 0; ni < 4; ni++) { acch[mi][ni][0] = 0u; acch[mi][ni][1] = 0u; }
        } else {
            #pragma unroll
            for (int mi = 0; mi < 4; mi++)
                #pragma unroll
                for (int ni = 0; ni < 4; ni++)
                    #pragma unroll
                    for (int j = 0; j < 4; j++) accf[mi][ni][j] = 0.0f;
        }

        issue(0, 0);
        issue(1, 1);

        for (int k = 0; k < nk; k++) {
            int st = k % 3;
            if (k + 1 < nk) asm volatile("cp.async.wait_group 1;" ::: "memory");
            else            asm volatile("cp.async.wait_group 0;" ::: "memory");
            __syncthreads();                   // single sync per iteration
            if (k + 2 < nk) issue(k + 2, (k + 2) % 3);

            uint32_t sb = smb + (uint32_t)st * STAGE_B;
            uint32_t bF[2][4][2];
            #pragma unroll
            for (int ks = 0; ks < 2; ks++) {
                uint32_t koffB = (uint32_t)(((ks * 2 + cB) ^ swB) << 4);
                uint32_t tmp[4];
                ldsm4(tmp, sb + laneB + koffB);
                bF[ks][0][0] = tmp[0]; bF[ks][0][1] = tmp[1];
                bF[ks][1][0] = tmp[2]; bF[ks][1][1] = tmp[3];
                ldsm4(tmp, sb + laneB + 1024 + koffB);
                bF[ks][2][0] = tmp[0]; bF[ks][2][1] = tmp[1];
                bF[ks][3][0] = tmp[2]; bF[ks][3][1] = tmp[3];
            }
            #pragma unroll
            for (int mi = 0; mi < 4; mi++) {
                uint32_t aF[2][4];
                ldsm4(aF[0], sb + laneA + (uint32_t)(mi * 1024) + koffA0);
                ldsm4(aF[1], sb + laneA + (uint32_t)(mi * 1024) + koffA1);
                #pragma unroll
                for (int ni = 0; ni < 4; ni++) {
                    if constexpr (ACC16) {
                        mma16h(acch[mi][ni], aF[0], bF[0][ni]);
                        mma16h(acch[mi][ni], aF[1], bF[1][ni]);
                    } else {
                        mma16(accf[mi][ni], aF[0], bF[0][ni]);
                        mma16(accf[mi][ni], aF[1], bF[1][ni]);
                    }
                }
            }
        }

        // extract tile (mi,ni) accumulator as 4 floats (single promotion)
        auto getc = [&](int mi, int ni, float* c) {
            if constexpr (ACC16) {
                float2 f0 = __half22float2(*(__half2*)&acch[mi][ni][0]);
                float2 f1 = __half22float2(*(__half2*)&acch[mi][ni][1]);
                c[0] = f0.x; c[1] = f0.y; c[2] = f1.x; c[3] = f1.y;
            } else {
                c[0] = accf[mi][ni][0]; c[1] = accf[mi][ni][1];
                c[2] = accf[mi][ni][2]; c[3] = accf[mi][ni][3];
            }
        };

        if (!sym) {
            float* Cp = C_ns + (long)(bi * 128) * ldC + bj * 128;
            #pragma unroll
            for (int mi = 0; mi < 4; mi++) {
                int row = (wid >> 2) * 64 + mi * 16 + g;
                #pragma unroll
                for (int ni = 0; ni < 4; ni++) {
                    int col = (wid & 3) * 32 + ni * 8 + q * 2;
                    float c[4]; getc(mi, ni, c);
                    *(float2*)&Cp[(long)row * ldC + col]       = make_float2(c[0], c[1]);
                    *(float2*)&Cp[(long)(row + 8) * ldC + col] = make_float2(c[2], c[3]);
                }
            }
        } else {
            __syncthreads();                  // stages done; reuse smem
            float* eb = (float*)smu;          // 128 x 132 staging tile
            #pragma unroll
            for (int mi = 0; mi < 4; mi++) {
                int row = (wid >> 2) * 64 + mi * 16 + g;
                #pragma unroll
                for (int ni = 0; ni < 4; ni++) {
                    int col = (wid & 3) * 32 + ni * 8 + q * 2;
                    float c[4]; getc(mi, ni, c);
                    *(float2*)&eb[row * 132 + col]       = make_float2(c[0], c[1]);
                    *(float2*)&eb[(row + 8) * 132 + col] = make_float2(c[2], c[3]);
                }
            }
            __syncthreads();
            float* Cn = C_s + csOff + (long)(bi * 128) * TT + bj * 128;
            #pragma unroll
            for (int i2 = 0; i2 < 16; i2++) {
                int id = t + i2 * 256;
                int r = id >> 5, c4 = (id & 31) * 4;
                *(float4*)&Cn[(long)r * TT + c4] = *(float4*)&eb[r * 132 + c4];
            }
            if (bi != bj) {
                float* Cm = C_s + csOff + (long)(bj * 128) * TT + bi * 128;
                #pragma unroll
                for (int i2 = 0; i2 < 16; i2++) {
                    int id = t + i2 * 256;
                    int rr = id & 127, c4 = (id >> 7) * 4;   // conflict-free map
                    float4 v;
                    v.x = eb[(c4 + 0) * 132 + rr];
                    v.y = eb[(c4 + 1) * 132 + rr];
                    v.z = eb[(c4 + 2) * 132 + rr];
                    v.w = eb[(c4 + 3) * 132 + rr];
                    *(float4*)&Cm[(long)rr * TT + c4] = v;
                }
            }
        }
        __syncthreads();   // next tile's cp.async must not race this tile's reads
    }
}

// --------------------------------- launch --------------------------------------
extern "C" void kernel_launch(void* const* d_in, const int* in_sizes, int n_in,
                              void* d_out, int out_size) {
    const float* key_soft = (const float*)d_in[0];   // [16,1024,256]
    const float* keys     = (const float*)d_in[1];   // [512,256]
    const float* vparams  = (const float*)d_in[2];   // [512,256]
    float* out = (float*)d_out;

    float* o_idx  = out;                             // [16384]
    float* o_vw   = o_idx  + MR;                     // [16384,256]
    float* o_hard = o_vw   + (long)MR * DD;          // [16384,256]
    float* o_vpss = o_hard + (long)MR * DD;          // [16,1024,1024]
    float* o_vpsh = o_vpss + (long)MR * TT;          // [16384,512]
    float* o_kss  = o_vpsh + (long)MR * NE;          // [16,1024,1024]
    float* o_ksh  = o_kss  + (long)MR * TT;          // [16384,512]

    __half *p_ksn_h, *p_wh, *p_keys_h, *p_vpn_h, *p_vpnT_h, *p_vwh;
    float *p_ksn_f, *p_keys_f, *p_vpn;
    cudaGetSymbolAddress((void**)&p_ksn_h,  g_ksn_h);
    cudaGetSymbolAddress((void**)&p_ksn_f,  g_ksn_f);
    cudaGetSymbolAddress((void**)&p_wh,     g_wh);
    cudaGetSymbolAddress((void**)&p_keys_h, g_keys_h);
    cudaGetSymbolAddress((void**)&p_keys_f, g_keys_f);
    cudaGetSymbolAddress((void**)&p_vpn,    g_vp_norm);
    cudaGetSymbolAddress((void**)&p_vpn_h,  g_vpn_h);
    cudaGetSymbolAddress((void**)&p_vpnT_h, g_vpnT_h);
    cudaGetSymbolAddress((void**)&p_vwh,    g_vwh);

    const int SMX = 128 * 132 * 4;        // 67584: sym epilogue (>= stage bytes)
    const int S1  = 3 * STAGE_B;          // 49152: stages only (nonsym-only call)
    cudaFuncSetAttribute(gemm_h<true>,
                         cudaFuncAttributeMaxDynamicSharedMemorySize, SMX);
    cudaFuncSetAttribute(gemm_h<false>,
                         cudaFuncAttributeMaxDynamicSharedMemorySize, S1);

    // 1) normalize codebooks + inputs (fp32 + fp16 copies)
    rownorm_hl<<<NE / 16, 256>>>(keys,    p_keys_f, p_keys_h, NE);
    rownorm_hl<<<NE / 16, 256>>>(vparams, p_vpn,    p_vpn_h,  NE);
    transpose_vp<<<dim3(DD / 32, NE / 32), dim3(32, 32)>>>();
    rownorm_hl<<<MR / 16, 256>>>(key_soft, p_ksn_f, p_ksn_h, MR);

    // 2) FUSED persistent: score_ksh (512 nonsym) + score_kss (576 sym), fp16-acc
    gemm_h<true><<<NSLOTS, 256, SMX>>>(
        p_ksn_h, p_keys_h, o_ksh, DD, NE, NE / 128, 512, 512 + 36 * BB,
        p_ksn_h, o_kss);

    // 3) warp-per-row softmax + exact-argmax correction + hard gather
    softmax_argmax<<<MR / 8, 256>>>(o_ksh, o_idx, o_hard);

    // 4) vw_raw = w @ vp_norm  [16384,256] — fp32-acc (long-K small-increment sum)
    gemm_h<false><<<(DD / 128) * (MR / 128), 256, S1>>>(
        p_wh, p_vpnT_h, o_vw, NE, DD, DD / 128,
        (DD / 128) * (MR / 128), (DD / 128) * (MR / 128),
        nullptr, nullptr);

    // 5) normalize vparams_w: fp32 in place + fp16 copy
    rownorm_hl<<<MR / 16, 256>>>(o_vw, o_vw, p_vwh, MR);

    // 6) FUSED persistent: score_vpsh (512 nonsym) + score_vpss (576 sym), fp16-acc
    gemm_h<true><<<NSLOTS, 256, SMX>>>(
        p_vwh, p_vpn_h, o_vpsh, DD, NE, NE / 128, 512, 512 + 36 * BB,
        p_vwh, o_vpss);
}

// round 14
// speedup vs baseline: 1.0904x; 1.0904x over previous
#include <cuda_runtime.h>
#include <cuda_fp16.h>
#include <math.h>
#include <stdint.h>

// Problem dims (fixed by the dataset)
#define BB   16
#define TT   1024
#define DD   256        // key_dim == e_dim
#define NE   512        // codebook size
#define MR   (BB*TT)    // 16384 rows

// ---------------- scratch (__device__ globals: allocation-free) ----------------
__device__ __half g_ksn_h[MR * DD];     // normalized key_soft, fp16
__device__ float  g_ksn_f[MR * DD];     // normalized key_soft, fp32 (argmax check)
__device__ __half g_wh[MR * NE];        // softmax weights fp16
__device__ __half g_keys_h[NE * DD];
__device__ float  g_keys_f[NE * DD];    // fp32 keys_norm (argmax check)
__device__ float  g_vp_norm[NE * DD];   // fp32 (exact gather source)
__device__ __half g_vpn_h[NE * DD];
__device__ __half g_vpnT_h[DD * NE];    // vp_norm transposed fp16 [E, n_e]
__device__ __half g_vwh[MR * DD];       // normalized vparams_w fp16

// =============================== aux kernels ===================================
// L2 normalize, 256 cols, 2 rows per warp (MLP=2); optional fp32 + fp16 outputs
__global__ void rownorm_hl(const float* __restrict__ in, float* __restrict__ of,
                           __half* __restrict__ oh, int nrows) {
    long w = (long)((blockIdx.x * blockDim.x + threadIdx.x) >> 5) * 2;
    int lane = threadIdx.x & 31;
    if (w >= nrows) return;
    const float4* ip0 = (const float4*)(in + w * 256);
    const float4* ip1 = (const float4*)(in + (w + 1) * 256);
    float4 a0 = ip0[lane], a1 = ip0[lane + 32];
    float4 b0 = ip1[lane], b1 = ip1[lane + 32];
    float s0 = a0.x*a0.x + a0.y*a0.y + a0.z*a0.z + a0.w*a0.w
             + a1.x*a1.x + a1.y*a1.y + a1.z*a1.z + a1.w*a1.w;
    float s1 = b0.x*b0.x + b0.y*b0.y + b0.z*b0.z + b0.w*b0.w
             + b1.x*b1.x + b1.y*b1.y + b1.z*b1.z + b1.w*b1.w;
    #pragma unroll
    for (int o = 16; o; o >>= 1) {
        s0 += __shfl_xor_sync(0xffffffffu, s0, o);
        s1 += __shfl_xor_sync(0xffffffffu, s1, o);
    }
    float k0 = 1.0f / fmaxf(sqrtf(s0), 1e-12f);
    float k1 = 1.0f / fmaxf(sqrtf(s1), 1e-12f);
    float4 r0 = make_float4(a0.x*k0, a0.y*k0, a0.z*k0, a0.w*k0);
    float4 r1 = make_float4(a1.x*k0, a1.y*k0, a1.z*k0, a1.w*k0);
    float4 r2 = make_float4(b0.x*k1, b0.y*k1, b0.z*k1, b0.w*k1);
    float4 r3 = make_float4(b1.x*k1, b1.y*k1, b1.z*k1, b1.w*k1);
    if (of) {
        float4* op0 = (float4*)(of + w * 256);
        float4* op1 = (float4*)(of + (w + 1) * 256);
        op0[lane] = r0; op0[lane + 32] = r1;
        op1[lane] = r2; op1[lane + 32] = r3;
    }
    __half2* hp0 = (__half2*)(oh + w * 256);
    __half2* hp1 = (__half2*)(oh + (w + 1) * 256);
    hp0[lane*2]        = __floats2half2_rn(r0.x, r0.y);
    hp0[lane*2+1]      = __floats2half2_rn(r0.z, r0.w);
    hp0[64 + lane*2]   = __floats2half2_rn(r1.x, r1.y);
    hp0[64 + lane*2+1] = __floats2half2_rn(r1.z, r1.w);
    hp1[lane*2]        = __floats2half2_rn(r2.x, r2.y);
    hp1[lane*2+1]      = __floats2half2_rn(r2.z, r2.w);
    hp1[64 + lane*2]   = __floats2half2_rn(r3.x, r3.y);
    hp1[64 + lane*2+1] = __floats2half2_rn(r3.z, r3.w);
}

__global__ void transpose_vp() {
    __shared__ float tile[32][33];
    int x = blockIdx.x * 32 + threadIdx.x;
    int y = blockIdx.y * 32 + threadIdx.y;
    tile[threadIdx.y][threadIdx.x] = g_vp_norm[y * 256 + x];
    __syncthreads();
    int tx = blockIdx.y * 32 + threadIdx.x;
    int ty = blockIdx.x * 32 + threadIdx.y;
    g_vpnT_h[ty * 512 + tx] = __float2half_rn(tile[threadIdx.x][threadIdx.y]);
}

// warp-per-row softmax + exact-argmax (fp32 candidate re-check) + hard gather
__global__ void softmax_argmax(const float* __restrict__ ksh,
                               float* __restrict__ out_idx,
                               float* __restrict__ out_hard) {
    int r = (blockIdx.x * blockDim.x + threadIdx.x) >> 5;
    int lane = threadIdx.x & 31;
    if (r >= MR) return;
    const float4* row4 = (const float4*)(ksh + (long)r * NE);
    float4 v[4];
    #pragma unroll
    for (int i = 0; i < 4; i++) v[i] = row4[i * 32 + lane];
    // warp max
    float m = -2e30f;
    #pragma unroll
    for (int i = 0; i < 4; i++)
        m = fmaxf(m, fmaxf(fmaxf(v[i].x, v[i].y), fmaxf(v[i].z, v[i].w)));
    #pragma unroll
    for (int o = 16; o; o >>= 1) m = fmaxf(m, __shfl_xor_sync(0xffffffffu, m, o));

    // fp32 query row (for exact re-check)
    const float4* xr4 = (const float4*)(g_ksn_f + (long)r * 256);
    float4 x0 = xr4[lane * 2], x1 = xr4[lane * 2 + 1];

    // candidate mask: fp16 dot error (input rounding + fp16-acc chain) << eps
    const float eps = 8e-3f;
    unsigned pend = 0;
    #pragma unroll
    for (int i = 0; i < 4; i++) {
        if (v[i].x >= m - eps) pend |= 1u << (i * 4 + 0);
        if (v[i].y >= m - eps) pend |= 1u << (i * 4 + 1);
        if (v[i].z >= m - eps) pend |= 1u << (i * 4 + 2);
        if (v[i].w >= m - eps) pend |= 1u << (i * 4 + 3);
    }
    float bv = -2e30f; int bi = 1 << 30;
    while (true) {
        unsigned act = __ballot_sync(0xffffffffu, pend != 0);
        if (!act) break;
        int leader = __ffs(act) - 1;
        int slot = (pend ? __ffs(pend) - 1 : 0);
        slot = __shfl_sync(0xffffffffu, slot, leader);
        int j = (slot >> 2) * 128 + leader * 4 + (slot & 3);
        const float4* kp = (const float4*)(g_keys_f + (long)j * 256);
        float4 u0 = kp[lane * 2], u1 = kp[lane * 2 + 1];
        float d = u0.x*x0.x + u0.y*x0.y + u0.z*x0.z + u0.w*x0.w
                + u1.x*x1.x + u1.y*x1.y + u1.z*x1.z + u1.w*x1.w;
        #pragma unroll
        for (int o = 16; o; o >>= 1) d += __shfl_xor_sync(0xffffffffu, d, o);
        if (d > bv || (d == bv && j < bi)) { bv = d; bi = j; }
        if (lane == leader) pend &= pend - 1;
    }

    // softmax (fp16-accurate scores: fine for w)
    float e[16];
    float sum = 0.0f;
    #pragma unroll
    for (int i = 0; i < 4; i++) {
        e[i*4+0] = expf(v[i].x - m); e[i*4+1] = expf(v[i].y - m);
        e[i*4+2] = expf(v[i].z - m); e[i*4+3] = expf(v[i].w - m);
        sum += e[i*4+0] + e[i*4+1] + e[i*4+2] + e[i*4+3];
    }
    #pragma unroll
    for (int o = 16; o; o >>= 1) sum += __shfl_xor_sync(0xffffffffu, sum, o);
    float inv = 1.0f / sum;
    __half2* wp = (__half2*)(g_wh + (long)r * NE);
    #pragma unroll
    for (int i = 0; i < 4; i++) {
        wp[i*64 + lane*2]     = __floats2half2_rn(e[i*4+0]*inv, e[i*4+1]*inv);
        wp[i*64 + lane*2 + 1] = __floats2half2_rn(e[i*4+2]*inv, e[i*4+3]*inv);
    }
    if (lane == 0) out_idx[r] = (float)bi;
    const float4* vp4 = (const float4*)(g_vp_norm + (long)bi * 256);
    float4* oh4 = (float4*)(out_hard + (long)r * 256);
    oh4[lane*2]     = vp4[lane*2];
    oh4[lane*2 + 1] = vp4[lane*2 + 1];
}

// ============= fp16 mma.sync GEMM with ldmatrix (m16n8k16, sm_80+) =============
// Unified kernel: blockIdx.x < nsCount  -> nonsym tile of C_ns = A_ns @ B_ns^T
//                 blockIdx.x >= nsCount -> symmetric Gram tile (batched, T=1024)
// Block tile 128x128, BK=64, 3-stage cp.async, 8 warps x (64x32), 2 CTAs/SM.
// SMEM per stage: A[128 rows][64 halves=128B] + B same; chunk swizzle
// c ^ (row&7): conflict-free for 16B cp.async writes AND all ldmatrix phases.
// ACC16: fp16 accumulators chained across the whole k-loop; promoted once.
__device__ __forceinline__ void cp16(uint32_t saddr, const void* g) {
    asm volatile("cp.async.cg.shared.global [%0], [%1], 16;"
                 :: "r"(saddr), "l"(g) : "memory");
}
__device__ __forceinline__ void ldsm4(uint32_t* r, uint32_t addr) {
    asm volatile("ldmatrix.sync.aligned.m8n8.x4.shared.b16 {%0,%1,%2,%3}, [%4];"
                 : "=r"(r[0]), "=r"(r[1]), "=r"(r[2]), "=r"(r[3]) : "r"(addr));
}
__device__ __forceinline__ void mma16(float* d, const uint32_t* a, const uint32_t* b) {
    asm volatile(
        "mma.sync.aligned.m16n8k16.row.col.f32.f16.f16.f32 "
        "{%0,%1,%2,%3}, {%4,%5,%6,%7}, {%8,%9}, {%0,%1,%2,%3};"
        : "+f"(d[0]), "+f"(d[1]), "+f"(d[2]), "+f"(d[3])
        : "r"(a[0]), "r"(a[1]), "r"(a[2]), "r"(a[3]), "r"(b[0]), "r"(b[1]));
}
__device__ __forceinline__ void mma16h(uint32_t* d, const uint32_t* a, const uint32_t* b) {
    asm volatile(
        "mma.sync.aligned.m16n8k16.row.col.f16.f16.f16.f16 "
        "{%0,%1}, {%2,%3,%4,%5}, {%6,%7}, {%0,%1};"
        : "+r"(d[0]), "+r"(d[1])
        : "r"(a[0]), "r"(a[1]), "r"(a[2]), "r"(a[3]), "r"(b[0]), "r"(b[1]));
}

#define STAGE_B 32768   // bytes per stage (A 16384 + B 16384), BK=64

template<bool ACC16>
__global__ __launch_bounds__(256, 2) void gemm_h(
    const __half* __restrict__ A_ns, const __half* __restrict__ B_ns,
    float* __restrict__ C_ns, int K, int ldC, int ntX, int nsCount,
    const __half* __restrict__ A_s, float* __restrict__ C_s)
{
    extern __shared__ uint32_t smu[];
    const int t = threadIdx.x;
    const int wid = t >> 5, lane = t & 31;
    const int g = lane >> 2, q = lane & 3;

    const int x = blockIdx.x;
    const bool sym = (x >= nsCount);
    int bi, bj;
    const __half *Ah, *Bh;
    long csOff = 0;
    if (!sym) {
        bi = x / ntX; bj = x % ntX;
        Ah = A_ns + (long)(bi * 128) * K;
        Bh = B_ns + (long)(bj * 128) * K;
    } else {
        int xs = x - nsCount;
        int bz = xs / 36, u = xs % 36, i = 0;
        while (u >= 8 - i) { u -= 8 - i; i++; }  // 36 pairs, i<=j
        bi = i; bj = i + u;
        const __half* base = A_s + (long)bz * TT * DD;   // K == DD here
        Ah = base + (long)(bi * 128) * K;
        Bh = base + (long)(bj * 128) * K;
        csOff = (long)bz * TT * TT;
    }

    uint32_t smb = (uint32_t)__cvta_generic_to_shared(smu);

    // ---- writer precompute: 8 x 16B cp.async per thread (4 A rows, 4 B rows)
    const int wr = t >> 3, wc = t & 7;                   // row 0..31, chunk 0..7
    const uint32_t wdst = (uint32_t)(wr * 128 + ((wc ^ (wr & 7)) << 4));
    const long  gsrc  = (long)wr * K + wc * 8;           // halves
    const long  gstep = (long)32 * K;                    // 32-row step (halves)

    auto issue = [&](int kc, int st) {
        uint32_t sb = smb + (uint32_t)st * STAGE_B;
        const __half* ap = Ah + gsrc + kc * 64;
        const __half* bp = Bh + gsrc + kc * 64;
        #pragma unroll
        for (int r4 = 0; r4 < 4; r4++) {
            cp16(sb + wdst + r4 * 4096,         ap + r4 * gstep);
            cp16(sb + 16384 + wdst + r4 * 4096, bp + r4 * gstep);
        }
        asm volatile("cp.async.commit_group;" ::: "memory");
    };

    // ---- reader precompute: ldmatrix lane addresses (128B rows, 8 chunks)
    const int mbase = (wid >> 2) * 64, nbase = (wid & 3) * 32;
    const int rA  = (lane & 7) + ((lane >> 3) & 1) * 8;  // row within 16-row tile
    const int cA  = lane >> 4;                           // 16B-chunk bit within k-step
    const int swA = rA & 7;
    const uint32_t laneA = (uint32_t)((mbase + rA) * 128);
    const int rB  = ((lane >> 4) << 3) + (lane & 7);
    const int cB  = (lane >> 3) & 1;
    const int swB = rB & 7;
    const uint32_t laneB = (uint32_t)(16384 + (nbase + rB) * 128);

    float    accf[4][4][4];
    uint32_t acch[4][4][2];
    if constexpr (ACC16) {
        #pragma unroll
        for (int mi = 0; mi < 4; mi++)
            #pragma unroll
            for (int ni = 0; ni < 4; ni++) { acch[mi][ni][0] = 0u; acch[mi][ni][1] = 0u; }
    } else {
        #pragma unroll
        for (int mi = 0; mi < 4; mi++)
            #pragma unroll
            for (int ni = 0; ni < 4; ni++)
                #pragma unroll
                for (int j = 0; j < 4; j++) accf[mi][ni][j] = 0.0f;
    }

    const int nk = K >> 6;                // BK=64 chunks (4 for K=256, 8 for 512)
    issue(0, 0);
    issue(1, 1);

    for (int k = 0; k < nk; k++) {
        int st = k % 3;
        if (k + 1 < nk) asm volatile("cp.async.wait_group 1;" ::: "memory");
        else            asm volatile("cp.async.wait_group 0;" ::: "memory");
        __syncthreads();                   // single sync per chunk
        if (k + 2 < nk) issue(k + 2, (k + 2) % 3);

        uint32_t sb = smb + (uint32_t)st * STAGE_B;
        #pragma unroll
        for (int ks = 0; ks < 4; ks++) {   // 4 k-steps of 16 within BK=64
            uint32_t koffB = (uint32_t)((((ks << 1) + cB) ^ swB) << 4);
            uint32_t bF[4][2];
            {
                uint32_t tmp[4];
                ldsm4(tmp, sb + laneB + koffB);          // nt 0,1
                bF[0][0] = tmp[0]; bF[0][1] = tmp[1];
                bF[1][0] = tmp[2]; bF[1][1] = tmp[3];
                ldsm4(tmp, sb + laneB + 2048 + koffB);   // nt 2,3 (16 rows * 128B)
                bF[2][0] = tmp[0]; bF[2][1] = tmp[1];
                bF[3][0] = tmp[2]; bF[3][1] = tmp[3];
            }
            uint32_t koffA = (uint32_t)((((ks << 1) + cA) ^ swA) << 4);
            #pragma unroll
            for (int mi = 0; mi < 4; mi++) {
                uint32_t aF[4];
                ldsm4(aF, sb + laneA + (uint32_t)(mi * 2048) + koffA);
                #pragma unroll
                for (int ni = 0; ni < 4; ni++) {
                    if constexpr (ACC16) mma16h(acch[mi][ni], aF, bF[ni]);
                    else                 mma16(accf[mi][ni], aF, bF[ni]);
                }
            }
        }
    }

    // extract tile (mi,ni) accumulator as 4 floats (single promotion for ACC16)
    auto getc = [&](int mi, int ni, float* c) {
        if constexpr (ACC16) {
            float2 f0 = __half22float2(*(__half2*)&acch[mi][ni][0]);
            float2 f1 = __half22float2(*(__half2*)&acch[mi][ni][1]);
            c[0] = f0.x; c[1] = f0.y; c[2] = f1.x; c[3] = f1.y;
        } else {
            c[0] = accf[mi][ni][0]; c[1] = accf[mi][ni][1];
            c[2] = accf[mi][ni][2]; c[3] = accf[mi][ni][3];
        }
    };

    if (!sym) {
        float* Cp = C_ns + (long)(bi * 128) * ldC + bj * 128;
        #pragma unroll
        for (int mi = 0; mi < 4; mi++) {
            int row = (wid >> 2) * 64 + mi * 16 + g;
            #pragma unroll
            for (int ni = 0; ni < 4; ni++) {
                int col = (wid & 3) * 32 + ni * 8 + q * 2;
                float c[4]; getc(mi, ni, c);
                *(float2*)&Cp[(long)row * ldC + col]       = make_float2(c[0], c[1]);
                *(float2*)&Cp[(long)(row + 8) * ldC + col] = make_float2(c[2], c[3]);
            }
        }
    } else {
        __syncthreads();                  // stages done; reuse smem
        float* eb = (float*)smu;          // 128 x 132 staging tile
        #pragma unroll
        for (int mi = 0; mi < 4; mi++) {
            int row = (wid >> 2) * 64 + mi * 16 + g;
            #pragma unroll
            for (int ni = 0; ni < 4; ni++) {
                int col = (wid & 3) * 32 + ni * 8 + q * 2;
                float c[4]; getc(mi, ni, c);
                *(float2*)&eb[row * 132 + col]       = make_float2(c[0], c[1]);
                *(float2*)&eb[(row + 8) * 132 + col] = make_float2(c[2], c[3]);
            }
        }
        __syncthreads();
        float* Cn = C_s + csOff + (long)(bi * 128) * TT + bj * 128;
        #pragma unroll
        for (int i2 = 0; i2 < 16; i2++) {
            int id = t + i2 * 256;
            int r = id >> 5, c4 = (id & 31) * 4;
            *(float4*)&Cn[(long)r * TT + c4] = *(float4*)&eb[r * 132 + c4];
        }
        if (bi != bj) {
            float* Cm = C_s + csOff + (long)(bj * 128) * TT + bi * 128;
            #pragma unroll
            for (int i2 = 0; i2 < 16; i2++) {
                int id = t + i2 * 256;
                int rr = id & 127, c4 = (id >> 7) * 4;   // conflict-free map
                float4 v;
                v.x = eb[(c4 + 0) * 132 + rr];
                v.y = eb[(c4 + 1) * 132 + rr];
                v.z = eb[(c4 + 2) * 132 + rr];
                v.w = eb[(c4 + 3) * 132 + rr];
                *(float4*)&Cm[(long)rr * TT + c4] = v;
            }
        }
    }
}

// --------------------------------- launch --------------------------------------
extern "C" void kernel_launch(void* const* d_in, const int* in_sizes, int n_in,
                              void* d_out, int out_size) {
    const float* key_soft = (const float*)d_in[0];   // [16,1024,256]
    const float* keys     = (const float*)d_in[1];   // [512,256]
    const float* vparams  = (const float*)d_in[2];   // [512,256]
    float* out = (float*)d_out;

    float* o_idx  = out;                             // [16384]
    float* o_vw   = o_idx  + MR;                     // [16384,256]
    float* o_hard = o_vw   + (long)MR * DD;          // [16384,256]
    float* o_vpss = o_hard + (long)MR * DD;          // [16,1024,1024]
    float* o_vpsh = o_vpss + (long)MR * TT;          // [16384,512]
    float* o_kss  = o_vpsh + (long)MR * NE;          // [16,1024,1024]
    float* o_ksh  = o_kss  + (long)MR * TT;          // [16384,512]

    __half *p_ksn_h, *p_wh, *p_keys_h, *p_vpn_h, *p_vpnT_h, *p_vwh;
    float *p_ksn_f, *p_keys_f, *p_vpn;
    cudaGetSymbolAddress((void**)&p_ksn_h,  g_ksn_h);
    cudaGetSymbolAddress((void**)&p_ksn_f,  g_ksn_f);
    cudaGetSymbolAddress((void**)&p_wh,     g_wh);
    cudaGetSymbolAddress((void**)&p_keys_h, g_keys_h);
    cudaGetSymbolAddress((void**)&p_keys_f, g_keys_f);
    cudaGetSymbolAddress((void**)&p_vpn,    g_vp_norm);
    cudaGetSymbolAddress((void**)&p_vpn_h,  g_vpn_h);
    cudaGetSymbolAddress((void**)&p_vpnT_h, g_vpnT_h);
    cudaGetSymbolAddress((void**)&p_vwh,    g_vwh);

    const int SMX = 3 * STAGE_B;          // 98304 >= sym epilogue 67584
    cudaFuncSetAttribute(gemm_h<true>,
                         cudaFuncAttributeMaxDynamicSharedMemorySize, SMX);
    cudaFuncSetAttribute(gemm_h<false>,
                         cudaFuncAttributeMaxDynamicSharedMemorySize, SMX);

    // 1) normalize codebooks + inputs (fp32 + fp16 copies)
    rownorm_hl<<<NE / 16, 256>>>(keys,    p_keys_f, p_keys_h, NE);
    rownorm_hl<<<NE / 16, 256>>>(vparams, p_vpn,    p_vpn_h,  NE);
    transpose_vp<<<dim3(DD / 32, NE / 32), dim3(32, 32)>>>();
    rownorm_hl<<<MR / 16, 256>>>(key_soft, p_ksn_f, p_ksn_h, MR);

    // 2) FUSED: score_ksh (512 nonsym tiles) + score_kss (576 sym tiles), fp16-acc
    gemm_h<true><<<512 + 36 * BB, 256, SMX>>>(
        p_ksn_h, p_keys_h, o_ksh, DD, NE, NE / 128, 512,
        p_ksn_h, o_kss);

    // 3) warp-per-row softmax + exact-argmax correction + hard gather
    softmax_argmax<<<MR / 8, 256>>>(o_ksh, o_idx, o_hard);

    // 4) vw_raw = w @ vp_norm  [16384,256] — fp32-acc (long-K small-increment sum)
    gemm_h<false><<<(DD / 128) * (MR / 128), 256, SMX>>>(
        p_wh, p_vpnT_h, o_vw, NE, DD, DD / 128, (DD / 128) * (MR / 128),
        nullptr, nullptr);

    // 5) normalize vparams_w: fp32 in place + fp16 copy
    rownorm_hl<<<MR / 16, 256>>>(o_vw, o_vw, p_vwh, MR);

    // 6) FUSED: score_vpsh (512 nonsym tiles) + score_vpss (576 sym tiles), fp16-acc
    gemm_h<true><<<512 + 36 * BB, 256, SMX>>>(
        p_vwh, p_vpn_h, o_vpsh, DD, NE, NE / 128, 512,
        p_vwh, o_vpss);
}

// round 15
// speedup vs baseline: 1.1350x; 1.0409x over previous
#include <cuda_runtime.h>
#include <cuda_fp16.h>
#include <math.h>
#include <stdint.h>

// Problem dims (fixed by the dataset)
#define BB   16
#define TT   1024
#define DD   256        // key_dim == e_dim
#define NE   512        // codebook size
#define MR   (BB*TT)    // 16384 rows

// ---------------- scratch (__device__ globals: allocation-free) ----------------
__device__ __half g_ksn_h[MR * DD];     // normalized key_soft, fp16
__device__ __half g_wh[MR * NE];        // softmax weights fp16
__device__ __half g_keys_h[NE * DD];
__device__ float  g_keys_f[NE * DD];    // fp32 keys_norm (argmax check)
__device__ float  g_vp_norm[NE * DD];   // fp32 (exact gather source)
__device__ __half g_vpn_h[NE * DD];
__device__ __half g_vpnT_h[DD * NE];    // vp_norm transposed fp16 [E, n_e]
__device__ __half g_vwh[MR * DD];       // normalized vparams_w fp16

// =============================== aux kernels ===================================
// L2 normalize, 256 cols, 2 rows per warp (MLP=2); optional fp32 + fp16 outputs
__global__ void rownorm_hl(const float* __restrict__ in, float* __restrict__ of,
                           __half* __restrict__ oh, int nrows) {
    long w = (long)((blockIdx.x * blockDim.x + threadIdx.x) >> 5) * 2;
    int lane = threadIdx.x & 31;
    if (w >= nrows) return;
    const float4* ip0 = (const float4*)(in + w * 256);
    const float4* ip1 = (const float4*)(in + (w + 1) * 256);
    float4 a0 = ip0[lane], a1 = ip0[lane + 32];
    float4 b0 = ip1[lane], b1 = ip1[lane + 32];
    float s0 = a0.x*a0.x + a0.y*a0.y + a0.z*a0.z + a0.w*a0.w
             + a1.x*a1.x + a1.y*a1.y + a1.z*a1.z + a1.w*a1.w;
    float s1 = b0.x*b0.x + b0.y*b0.y + b0.z*b0.z + b0.w*b0.w
             + b1.x*b1.x + b1.y*b1.y + b1.z*b1.z + b1.w*b1.w;
    #pragma unroll
    for (int o = 16; o; o >>= 1) {
        s0 += __shfl_xor_sync(0xffffffffu, s0, o);
        s1 += __shfl_xor_sync(0xffffffffu, s1, o);
    }
    float k0 = 1.0f / fmaxf(sqrtf(s0), 1e-12f);
    float k1 = 1.0f / fmaxf(sqrtf(s1), 1e-12f);
    float4 r0 = make_float4(a0.x*k0, a0.y*k0, a0.z*k0, a0.w*k0);
    float4 r1 = make_float4(a1.x*k0, a1.y*k0, a1.z*k0, a1.w*k0);
    float4 r2 = make_float4(b0.x*k1, b0.y*k1, b0.z*k1, b0.w*k1);
    float4 r3 = make_float4(b1.x*k1, b1.y*k1, b1.z*k1, b1.w*k1);
    if (of) {
        float4* op0 = (float4*)(of + w * 256);
        float4* op1 = (float4*)(of + (w + 1) * 256);
        op0[lane] = r0; op0[lane + 32] = r1;
        op1[lane] = r2; op1[lane + 32] = r3;
    }
    __half2* hp0 = (__half2*)(oh + w * 256);
    __half2* hp1 = (__half2*)(oh + (w + 1) * 256);
    hp0[lane*2]        = __floats2half2_rn(r0.x, r0.y);
    hp0[lane*2+1]      = __floats2half2_rn(r0.z, r0.w);
    hp0[64 + lane*2]   = __floats2half2_rn(r1.x, r1.y);
    hp0[64 + lane*2+1] = __floats2half2_rn(r1.z, r1.w);
    hp1[lane*2]        = __floats2half2_rn(r2.x, r2.y);
    hp1[lane*2+1]      = __floats2half2_rn(r2.z, r2.w);
    hp1[64 + lane*2]   = __floats2half2_rn(r3.x, r3.y);
    hp1[64 + lane*2+1] = __floats2half2_rn(r3.z, r3.w);
}

// fused codebook prep: rows [0,NE) = keys -> keys_f/keys_h;
//                      rows [NE,2NE) = vparams -> vp_norm/vpn_h
__global__ void rownorm_codebooks(const float* __restrict__ keys,
                                  const float* __restrict__ vparams) {
    long w = (long)((blockIdx.x * blockDim.x + threadIdx.x) >> 5) * 2;
    int lane = threadIdx.x & 31;
    const float* in; float* of; __half* oh; long r;
    if (w < NE) { in = keys;    of = g_keys_f;  oh = g_keys_h; r = w; }
    else        { in = vparams; of = g_vp_norm; oh = g_vpn_h;  r = w - NE; }
    const float4* ip0 = (const float4*)(in + r * 256);
    const float4* ip1 = (const float4*)(in + (r + 1) * 256);
    float4 a0 = ip0[lane], a1 = ip0[lane + 32];
    float4 b0 = ip1[lane], b1 = ip1[lane + 32];
    float s0 = a0.x*a0.x + a0.y*a0.y + a0.z*a0.z + a0.w*a0.w
             + a1.x*a1.x + a1.y*a1.y + a1.z*a1.z + a1.w*a1.w;
    float s1 = b0.x*b0.x + b0.y*b0.y + b0.z*b0.z + b0.w*b0.w
             + b1.x*b1.x + b1.y*b1.y + b1.z*b1.z + b1.w*b1.w;
    #pragma unroll
    for (int o = 16; o; o >>= 1) {
        s0 += __shfl_xor_sync(0xffffffffu, s0, o);
        s1 += __shfl_xor_sync(0xffffffffu, s1, o);
    }
    float k0 = 1.0f / fmaxf(sqrtf(s0), 1e-12f);
    float k1 = 1.0f / fmaxf(sqrtf(s1), 1e-12f);
    float4 r0 = make_float4(a0.x*k0, a0.y*k0, a0.z*k0, a0.w*k0);
    float4 r1 = make_float4(a1.x*k0, a1.y*k0, a1.z*k0, a1.w*k0);
    float4 r2 = make_float4(b0.x*k1, b0.y*k1, b0.z*k1, b0.w*k1);
    float4 r3 = make_float4(b1.x*k1, b1.y*k1, b1.z*k1, b1.w*k1);
    float4* op0 = (float4*)(of + r * 256);
    float4* op1 = (float4*)(of + (r + 1) * 256);
    op0[lane] = r0; op0[lane + 32] = r1;
    op1[lane] = r2; op1[lane + 32] = r3;
    __half2* hp0 = (__half2*)(oh + r * 256);
    __half2* hp1 = (__half2*)(oh + (r + 1) * 256);
    hp0[lane*2]        = __floats2half2_rn(r0.x, r0.y);
    hp0[lane*2+1]      = __floats2half2_rn(r0.z, r0.w);
    hp0[64 + lane*2]   = __floats2half2_rn(r1.x, r1.y);
    hp0[64 + lane*2+1] = __floats2half2_rn(r1.z, r1.w);
    hp1[lane*2]        = __floats2half2_rn(r2.x, r2.y);
    hp1[lane*2+1]      = __floats2half2_rn(r2.z, r2.w);
    hp1[64 + lane*2]   = __floats2half2_rn(r3.x, r3.y);
    hp1[64 + lane*2+1] = __floats2half2_rn(r3.z, r3.w);
}

__global__ void transpose_vp() {
    __shared__ float tile[32][33];
    int x = blockIdx.x * 32 + threadIdx.x;
    int y = blockIdx.y * 32 + threadIdx.y;
    tile[threadIdx.y][threadIdx.x] = g_vp_norm[y * 256 + x];
    __syncthreads();
    int tx = blockIdx.y * 32 + threadIdx.x;
    int ty = blockIdx.x * 32 + threadIdx.y;
    g_vpnT_h[ty * 512 + tx] = __float2half_rn(tile[threadIdx.x][threadIdx.y]);
}

// warp-per-row softmax + exact-argmax (fp32 candidate re-check on RAW query:
// argmax_j <x_hat, k_hat_j> == argmax_j <x, k_hat_j>, scale-invariant) + gather
__global__ void softmax_argmax(const float* __restrict__ ksh,
                               const float* __restrict__ key_soft,
                               float* __restrict__ out_idx,
                               float* __restrict__ out_hard) {
    int r = (blockIdx.x * blockDim.x + threadIdx.x) >> 5;
    int lane = threadIdx.x & 31;
    if (r >= MR) return;
    const float4* row4 = (const float4*)(ksh + (long)r * NE);
    float4 v[4];
    #pragma unroll
    for (int i = 0; i < 4; i++) v[i] = row4[i * 32 + lane];
    // warp max
    float m = -2e30f;
    #pragma unroll
    for (int i = 0; i < 4; i++)
        m = fmaxf(m, fmaxf(fmaxf(v[i].x, v[i].y), fmaxf(v[i].z, v[i].w)));
    #pragma unroll
    for (int o = 16; o; o >>= 1) m = fmaxf(m, __shfl_xor_sync(0xffffffffu, m, o));

    // raw query row (re-check is scale-invariant)
    const float4* xr4 = (const float4*)(key_soft + (long)r * 256);
    float4 x0 = xr4[lane * 2], x1 = xr4[lane * 2 + 1];

    // candidate mask: fp16 dot error (input rounding + fp16-acc chain) << eps
    const float eps = 8e-3f;
    unsigned pend = 0;
    #pragma unroll
    for (int i = 0; i < 4; i++) {
        if (v[i].x >= m - eps) pend |= 1u << (i * 4 + 0);
        if (v[i].y >= m - eps) pend |= 1u << (i * 4 + 1);
        if (v[i].z >= m - eps) pend |= 1u << (i * 4 + 2);
        if (v[i].w >= m - eps) pend |= 1u << (i * 4 + 3);
    }
    float bv = -2e30f; int bi = 1 << 30;
    while (true) {
        unsigned act = __ballot_sync(0xffffffffu, pend != 0);
        if (!act) break;
        int leader = __ffs(act) - 1;
        int slot = (pend ? __ffs(pend) - 1 : 0);
        slot = __shfl_sync(0xffffffffu, slot, leader);
        int j = (slot >> 2) * 128 + leader * 4 + (slot & 3);
        const float4* kp = (const float4*)(g_keys_f + (long)j * 256);
        float4 u0 = kp[lane * 2], u1 = kp[lane * 2 + 1];
        float d = u0.x*x0.x + u0.y*x0.y + u0.z*x0.z + u0.w*x0.w
                + u1.x*x1.x + u1.y*x1.y + u1.z*x1.z + u1.w*x1.w;
        #pragma unroll
        for (int o = 16; o; o >>= 1) d += __shfl_xor_sync(0xffffffffu, d, o);
        if (d > bv || (d == bv && j < bi)) { bv = d; bi = j; }
        if (lane == leader) pend &= pend - 1;
    }

    // softmax (fp16-accurate scores: fine for w)
    float e[16];
    float sum = 0.0f;
    #pragma unroll
    for (int i = 0; i < 4; i++) {
        e[i*4+0] = expf(v[i].x - m); e[i*4+1] = expf(v[i].y - m);
        e[i*4+2] = expf(v[i].z - m); e[i*4+3] = expf(v[i].w - m);
        sum += e[i*4+0] + e[i*4+1] + e[i*4+2] + e[i*4+3];
    }
    #pragma unroll
    for (int o = 16; o; o >>= 1) sum += __shfl_xor_sync(0xffffffffu, sum, o);
    float inv = 1.0f / sum;
    __half2* wp = (__half2*)(g_wh + (long)r * NE);
    #pragma unroll
    for (int i = 0; i < 4; i++) {
        wp[i*64 + lane*2]     = __floats2half2_rn(e[i*4+0]*inv, e[i*4+1]*inv);
        wp[i*64 + lane*2 + 1] = __floats2half2_rn(e[i*4+2]*inv, e[i*4+3]*inv);
    }
    if (lane == 0) out_idx[r] = (float)bi;
    const float4* vp4 = (const float4*)(g_vp_norm + (long)bi * 256);
    float4* oh4 = (float4*)(out_hard + (long)r * 256);
    oh4[lane*2]     = vp4[lane*2];
    oh4[lane*2 + 1] = vp4[lane*2 + 1];
}

// ============= fp16 mma.sync GEMM with ldmatrix (m16n8k16, sm_80+) =============
// Unified kernel: blockIdx.x < nsCount  -> nonsym tile of C_ns = A_ns @ B_ns^T
//                 blockIdx.x >= nsCount -> symmetric Gram tile (batched, T=1024)
// Block tile 128x128, BK=64, 3-stage cp.async, 8 warps x (64x32), 2 CTAs/SM.
// SMEM per stage: A[128 rows][64 halves=128B] + B same; chunk swizzle
// c ^ (row&7): conflict-free for 16B cp.async writes AND all ldmatrix phases.
// ACC16: fp16 accumulators chained across the whole k-loop; promoted once.
__device__ __forceinline__ void cp16(uint32_t saddr, const void* g) {
    asm volatile("cp.async.cg.shared.global [%0], [%1], 16;"
                 :: "r"(saddr), "l"(g) : "memory");
}
__device__ __forceinline__ void ldsm4(uint32_t* r, uint32_t addr) {
    asm volatile("ldmatrix.sync.aligned.m8n8.x4.shared.b16 {%0,%1,%2,%3}, [%4];"
                 : "=r"(r[0]), "=r"(r[1]), "=r"(r[2]), "=r"(r[3]) : "r"(addr));
}
__device__ __forceinline__ void mma16(float* d, const uint32_t* a, const uint32_t* b) {
    asm volatile(
        "mma.sync.aligned.m16n8k16.row.col.f32.f16.f16.f32 "
        "{%0,%1,%2,%3}, {%4,%5,%6,%7}, {%8,%9}, {%0,%1,%2,%3};"
        : "+f"(d[0]), "+f"(d[1]), "+f"(d[2]), "+f"(d[3])
        : "r"(a[0]), "r"(a[1]), "r"(a[2]), "r"(a[3]), "r"(b[0]), "r"(b[1]));
}
__device__ __forceinline__ void mma16h(uint32_t* d, const uint32_t* a, const uint32_t* b) {
    asm volatile(
        "mma.sync.aligned.m16n8k16.row.col.f16.f16.f16.f16 "
        "{%0,%1}, {%2,%3,%4,%5}, {%6,%7}, {%0,%1};"
        : "+r"(d[0]), "+r"(d[1])
        : "r"(a[0]), "r"(a[1]), "r"(a[2]), "r"(a[3]), "r"(b[0]), "r"(b[1]));
}

#define STAGE_B 32768   // bytes per stage (A 16384 + B 16384), BK=64

template<bool ACC16>
__global__ __launch_bounds__(256, 2) void gemm_h(
    const __half* __restrict__ A_ns, const __half* __restrict__ B_ns,
    float* __restrict__ C_ns, int K, int ldC, int ntX, int nsCount,
    const __half* __restrict__ A_s, float* __restrict__ C_s)
{
    extern __shared__ uint32_t smu[];
    const int t = threadIdx.x;
    const int wid = t >> 5, lane = t & 31;
    const int g = lane >> 2, q = lane & 3;

    const int x = blockIdx.x;
    const bool sym = (x >= nsCount);
    int bi, bj;
    const __half *Ah, *Bh;
    long csOff = 0;
    if (!sym) {
        bi = x / ntX; bj = x % ntX;
        Ah = A_ns + (long)(bi * 128) * K;
        Bh = B_ns + (long)(bj * 128) * K;
    } else {
        int xs = x - nsCount;
        int bz = xs / 36, u = xs % 36, i = 0;
        while (u >= 8 - i) { u -= 8 - i; i++; }  // 36 pairs, i<=j
        bi = i; bj = i + u;
        const __half* base = A_s + (long)bz * TT * DD;   // K == DD here
        Ah = base + (long)(bi * 128) * K;
        Bh = base + (long)(bj * 128) * K;
        csOff = (long)bz * TT * TT;
    }

    uint32_t smb = (uint32_t)__cvta_generic_to_shared(smu);

    // ---- writer precompute: 8 x 16B cp.async per thread (4 A rows, 4 B rows)
    const int wr = t >> 3, wc = t & 7;                   // row 0..31, chunk 0..7
    const uint32_t wdst = (uint32_t)(wr * 128 + ((wc ^ (wr & 7)) << 4));
    const long  gsrc  = (long)wr * K + wc * 8;           // halves
    const long  gstep = (long)32 * K;                    // 32-row step (halves)

    auto issue = [&](int kc, int st) {
        uint32_t sb = smb + (uint32_t)st * STAGE_B;
        const __half* ap = Ah + gsrc + kc * 64;
        const __half* bp = Bh + gsrc + kc * 64;
        #pragma unroll
        for (int r4 = 0; r4 < 4; r4++) {
            cp16(sb + wdst + r4 * 4096,         ap + r4 * gstep);
            cp16(sb + 16384 + wdst + r4 * 4096, bp + r4 * gstep);
        }
        asm volatile("cp.async.commit_group;" ::: "memory");
    };

    // ---- reader precompute: ldmatrix lane addresses (128B rows, 8 chunks)
    const int mbase = (wid >> 2) * 64, nbase = (wid & 3) * 32;
    const int rA  = (lane & 7) + ((lane >> 3) & 1) * 8;  // row within 16-row tile
    const int cA  = lane >> 4;                           // 16B-chunk bit within k-step
    const int swA = rA & 7;
    const uint32_t laneA = (uint32_t)((mbase + rA) * 128);
    const int rB  = ((lane >> 4) << 3) + (lane & 7);
    const int cB  = (lane >> 3) & 1;
    const int swB = rB & 7;
    const uint32_t laneB = (uint32_t)(16384 + (nbase + rB) * 128);

    float    accf[4][4][4];
    uint32_t acch[4][4][2];
    if constexpr (ACC16) {
        #pragma unroll
        for (int mi = 0; mi < 4; mi++)
            #pragma unroll
            for (int ni = 0; ni < 4; ni++) { acch[mi][ni][0] = 0u; acch[mi][ni][1] = 0u; }
    } else {
        #pragma unroll
        for (int mi = 0; mi < 4; mi++)
            #pragma unroll
            for (int ni = 0; ni < 4; ni++)
                #pragma unroll
                for (int j = 0; j < 4; j++) accf[mi][ni][j] = 0.0f;
    }

    const int nk = K >> 6;                // BK=64 chunks (4 for K=256, 8 for 512)
    issue(0, 0);
    issue(1, 1);

    for (int k = 0; k < nk; k++) {
        int st = k % 3;
        if (k + 1 < nk) asm volatile("cp.async.wait_group 1;" ::: "memory");
        else            asm volatile("cp.async.wait_group 0;" ::: "memory");
        __syncthreads();                   // single sync per chunk
        if (k + 2 < nk) issue(k + 2, (k + 2) % 3);

        uint32_t sb = smb + (uint32_t)st * STAGE_B;
        #pragma unroll
        for (int ks = 0; ks < 4; ks++) {   // 4 k-steps of 16 within BK=64
            uint32_t koffB = (uint32_t)((((ks << 1) + cB) ^ swB) << 4);
            uint32_t bF[4][2];
            {
                uint32_t tmp[4];
                ldsm4(tmp, sb + laneB + koffB);          // nt 0,1
                bF[0][0] = tmp[0]; bF[0][1] = tmp[1];
                bF[1][0] = tmp[2]; bF[1][1] = tmp[3];
                ldsm4(tmp, sb + laneB + 2048 + koffB);   // nt 2,3 (16 rows * 128B)
                bF[2][0] = tmp[0]; bF[2][1] = tmp[1];
                bF[3][0] = tmp[2]; bF[3][1] = tmp[3];
            }
            uint32_t koffA = (uint32_t)((((ks << 1) + cA) ^ swA) << 4);
            #pragma unroll
            for (int mi = 0; mi < 4; mi++) {
                uint32_t aF[4];
                ldsm4(aF, sb + laneA + (uint32_t)(mi * 2048) + koffA);
                #pragma unroll
                for (int ni = 0; ni < 4; ni++) {
                    if constexpr (ACC16) mma16h(acch[mi][ni], aF, bF[ni]);
                    else                 mma16(accf[mi][ni], aF, bF[ni]);
                }
            }
        }
    }

    // extract tile (mi,ni) accumulator as 4 floats (single promotion for ACC16)
    auto getc = [&](int mi, int ni, float* c) {
        if constexpr (ACC16) {
            float2 f0 = __half22float2(*(__half2*)&acch[mi][ni][0]);
            float2 f1 = __half22float2(*(__half2*)&acch[mi][ni][1]);
            c[0] = f0.x; c[1] = f0.y; c[2] = f1.x; c[3] = f1.y;
        } else {
            c[0] = accf[mi][ni][0]; c[1] = accf[mi][ni][1];
            c[2] = accf[mi][ni][2]; c[3] = accf[mi][ni][3];
        }
    };

    // straight tile written directly from registers (both sym and nonsym)
    {
        float* Cp = sym ? (C_s + csOff + (long)(bi * 128) * TT + bj * 128)
                        : (C_ns + (long)(bi * 128) * ldC + bj * 128);
        int ld = sym ? TT : ldC;
        #pragma unroll
        for (int mi = 0; mi < 4; mi++) {
            int row = (wid >> 2) * 64 + mi * 16 + g;
            #pragma unroll
            for (int ni = 0; ni < 4; ni++) {
                int col = (wid & 3) * 32 + ni * 8 + q * 2;
                float c[4]; getc(mi, ni, c);
                *(float2*)&Cp[(long)row * ld + col]       = make_float2(c[0], c[1]);
                *(float2*)&Cp[(long)(row + 8) * ld + col] = make_float2(c[2], c[3]);
            }
        }
    }

    // mirrored write for off-diagonal sym tiles only (SMEM-staged transpose)
    if (sym && bi != bj) {
        __syncthreads();                  // stages done; reuse smem
        float* eb = (float*)smu;          // 128 x 132 staging tile
        #pragma unroll
        for (int mi = 0; mi < 4; mi++) {
            int row = (wid >> 2) * 64 + mi * 16 + g;
            #pragma unroll
            for (int ni = 0; ni < 4; ni++) {
                int col = (wid & 3) * 32 + ni * 8 + q * 2;
                float c[4]; getc(mi, ni, c);
                *(float2*)&eb[row * 132 + col]       = make_float2(c[0], c[1]);
                *(float2*)&eb[(row + 8) * 132 + col] = make_float2(c[2], c[3]);
            }
        }
        __syncthreads();
        float* Cm = C_s + csOff + (long)(bj * 128) * TT + bi * 128;
        #pragma unroll
        for (int i2 = 0; i2 < 16; i2++) {
            int id = t + i2 * 256;
            int rr = id & 127, c4 = (id >> 7) * 4;   // conflict-free map
            float4 v;
            v.x = eb[(c4 + 0) * 132 + rr];
            v.y = eb[(c4 + 1) * 132 + rr];
            v.z = eb[(c4 + 2) * 132 + rr];
            v.w = eb[(c4 + 3) * 132 + rr];
            *(float4*)&Cm[(long)rr * TT + c4] = v;
        }
    }
}

// --------------------------------- launch --------------------------------------
extern "C" void kernel_launch(void* const* d_in, const int* in_sizes, int n_in,
                              void* d_out, int out_size) {
    const float* key_soft = (const float*)d_in[0];   // [16,1024,256]
    const float* keys     = (const float*)d_in[1];   // [512,256]
    const float* vparams  = (const float*)d_in[2];   // [512,256]
    float* out = (float*)d_out;

    float* o_idx  = out;                             // [16384]
    float* o_vw   = o_idx  + MR;                     // [16384,256]
    float* o_hard = o_vw   + (long)MR * DD;          // [16384,256]
    float* o_vpss = o_hard + (long)MR * DD;          // [16,1024,1024]
    float* o_vpsh = o_vpss + (long)MR * TT;          // [16384,512]
    float* o_kss  = o_vpsh + (long)MR * NE;          // [16,1024,1024]
    float* o_ksh  = o_kss  + (long)MR * TT;          // [16384,512]

    __half *p_ksn_h, *p_wh, *p_keys_h, *p_vpn_h, *p_vpnT_h, *p_vwh;
    cudaGetSymbolAddress((void**)&p_ksn_h,  g_ksn_h);
    cudaGetSymbolAddress((void**)&p_wh,     g_wh);
    cudaGetSymbolAddress((void**)&p_keys_h, g_keys_h);
    cudaGetSymbolAddress((void**)&p_vpn_h,  g_vpn_h);
    cudaGetSymbolAddress((void**)&p_vpnT_h, g_vpnT_h);
    cudaGetSymbolAddress((void**)&p_vwh,    g_vwh);

    const int SMX = 3 * STAGE_B;          // 98304 >= sym epilogue 67584
    cudaFuncSetAttribute(gemm_h<true>,
                         cudaFuncAttributeMaxDynamicSharedMemorySize, SMX);
    cudaFuncSetAttribute(gemm_h<false>,
                         cudaFuncAttributeMaxDynamicSharedMemorySize, SMX);

    // 1) normalize codebooks (fused) + transpose + input rows (fp16 only)
    rownorm_codebooks<<<2 * NE / 16, 256>>>(keys, vparams);
    transpose_vp<<<dim3(DD / 32, NE / 32), dim3(32, 32)>>>();
    rownorm_hl<<<MR / 16, 256>>>(key_soft, nullptr, p_ksn_h, MR);

    // 2) FUSED: score_ksh (512 nonsym tiles) + score_kss (576 sym tiles), fp16-acc
    gemm_h<true><<<512 + 36 * BB, 256, SMX>>>(
        p_ksn_h, p_keys_h, o_ksh, DD, NE, NE / 128, 512,
        p_ksn_h, o_kss);

    // 3) warp-per-row softmax + exact-argmax (raw-query re-check) + hard gather
    softmax_argmax<<<MR / 8, 256>>>(o_ksh, key_soft, o_idx, o_hard);

    // 4) vw_raw = w @ vp_norm  [16384,256] — fp32-acc (long-K small-increment sum)
    gemm_h<false><<<(DD / 128) * (MR / 128), 256, SMX>>>(
        p_wh, p_vpnT_h, o_vw, NE, DD, DD / 128, (DD / 128) * (MR / 128),
        nullptr, nullptr);

    // 5) normalize vparams_w: fp32 in place + fp16 copy
    rownorm_hl<<<MR / 16, 256>>>(o_vw, o_vw, p_vwh, MR);

    // 6) FUSED: score_vpsh (512 nonsym tiles) + score_vpss (576 sym tiles), fp16-acc
    gemm_h<true><<<512 + 36 * BB, 256, SMX>>>(
        p_vwh, p_vpn_h, o_vpsh, DD, NE, NE / 128, 512,
        p_vwh, o_vpss);
}